// round 1
// baseline (speedup 1.0000x reference)
#include <cuda_runtime.h>
#include <cstddef>

#define NGN 100000
#define NDN 100000
#define NE  400000
#define NEL 200000
#define CC  128

#define MT 64
#define KC 32
#define XS_STRIDE 36    // 64 rows * 36 floats  (16B-aligned float4 slots, bank-shifted)
#define WS_STRIDE 132   // 32 rows * 132 floats (16B-aligned float4 slots, bank-shifted)

// Scratch (device globals; no allocation allowed in kernel_launch)
__device__ __align__(16) float g_ug[(size_t)NGN * CC];
__device__ __align__(16) float g_ud[(size_t)NDN * CC];
__device__ unsigned char g_mask_g[NGN];
__device__ unsigned char g_mask_d[NDN];

// ---------------------------------------------------------------------------
// Degree masks: node receives any edge => mask 1
// ---------------------------------------------------------------------------
__global__ void init_masks_kernel() {
    int i = blockIdx.x * blockDim.x + threadIdx.x;
    if (i < NGN) g_mask_g[i] = 0;
    if (i < NDN) g_mask_d[i] = 0;
}

__global__ void scatter_masks_kernel(const int* __restrict__ dst_g2d,
                                     const int* __restrict__ dst_d2g) {
    int e = blockIdx.x * blockDim.x + threadIdx.x;
    if (e < NE) {
        g_mask_d[dst_g2d[e]] = 1;   // g2d edges land on diseases
        g_mask_g[dst_d2g[e]] = 1;   // d2g edges land on genes
    }
}

// ---------------------------------------------------------------------------
// GEMM: out[M, 128] = act(A[M,128] @ W[128,128] + bias) * mask
//   do_relu=1: v = mask[r] ? max(v,0) : 0   (mask may be null -> plain relu)
//   do_relu=0: v = v (+ bias if given)
// Tile: 64x128 per block, 256 threads, 4x8 register tile per thread, KC=32.
// ---------------------------------------------------------------------------
__global__ __launch_bounds__(256) void gemm128_kernel(
    const float* __restrict__ A, const float* __restrict__ W,
    const float* __restrict__ bias, const unsigned char* __restrict__ mask,
    float* __restrict__ out, int M, int do_relu)
{
    __shared__ float xs[MT * XS_STRIDE];   // ~9.2 KB
    __shared__ float ws[KC * WS_STRIDE];   // ~16.9 KB

    const int tid = threadIdx.x;
    const int tx = tid & 15;          // 16 column groups (8 cols each)
    const int ty = tid >> 4;          // 16 row groups (4 rows each)
    const int row0 = blockIdx.x * MT;

    float acc[4][8];
    #pragma unroll
    for (int i = 0; i < 4; ++i)
        #pragma unroll
        for (int j = 0; j < 8; ++j) acc[i][j] = 0.0f;

    for (int kc = 0; kc < CC; kc += KC) {
        // Stage A tile: 64 rows x 32 k = 512 float4
        #pragma unroll
        for (int t = 0; t < 2; ++t) {
            int f = tid + t * 256;            // 0..511
            int r = f >> 3;                   // 8 float4 per row
            int kp = (f & 7) << 2;
            float4 v = make_float4(0.f, 0.f, 0.f, 0.f);
            if (row0 + r < M)
                v = *(const float4*)(A + (size_t)(row0 + r) * CC + kc + kp);
            *(float4*)(xs + r * XS_STRIDE + kp) = v;
        }
        // Stage W tile: 32 k-rows x 128 n = 1024 float4
        #pragma unroll
        for (int t = 0; t < 4; ++t) {
            int f = tid + t * 256;            // 0..1023
            int k = f >> 5;                   // 32 float4 per row
            int np = (f & 31) << 2;
            float4 v = *(const float4*)(W + (size_t)(kc + k) * CC + np);
            *(float4*)(ws + k * WS_STRIDE + np) = v;
        }
        __syncthreads();

        #pragma unroll
        for (int k = 0; k < KC; ++k) {
            float a[4];
            #pragma unroll
            for (int i = 0; i < 4; ++i)
                a[i] = xs[(ty * 4 + i) * XS_STRIDE + k];
            const float4 w0 = *(const float4*)(ws + k * WS_STRIDE + tx * 8);
            const float4 w1 = *(const float4*)(ws + k * WS_STRIDE + tx * 8 + 4);
            float wv[8] = {w0.x, w0.y, w0.z, w0.w, w1.x, w1.y, w1.z, w1.w};
            #pragma unroll
            for (int i = 0; i < 4; ++i)
                #pragma unroll
                for (int j = 0; j < 8; ++j)
                    acc[i][j] = fmaf(a[i], wv[j], acc[i][j]);
        }
        __syncthreads();
    }

    // Epilogue
    float bv[8];
    #pragma unroll
    for (int j = 0; j < 8; ++j)
        bv[j] = bias ? bias[tx * 8 + j] : 0.0f;

    #pragma unroll
    for (int i = 0; i < 4; ++i) {
        int r = row0 + ty * 4 + i;
        if (r < M) {
            float mm = 1.0f;
            if (do_relu && mask) mm = (float)mask[r];
            float4 o0, o1;
            float o[8];
            #pragma unroll
            for (int j = 0; j < 8; ++j) {
                float v = acc[i][j] + bv[j];
                if (do_relu) v = fmaxf(v, 0.0f) * mm;
                o[j] = v;
            }
            o0 = make_float4(o[0], o[1], o[2], o[3]);
            o1 = make_float4(o[4], o[5], o[6], o[7]);
            float* dst = out + (size_t)r * CC + tx * 8;
            *(float4*)dst = o0;
            *(float4*)(dst + 4) = o1;
        }
    }
}

// ---------------------------------------------------------------------------
// Link prediction head: one warp per labeled edge.
// pred[e] = relu(u_g[row[e]] + u_d[col[e]]) . W2 + b2     (b1 folded into u_d)
// ---------------------------------------------------------------------------
__global__ __launch_bounds__(256) void pred_kernel(
    const int* __restrict__ erow, const int* __restrict__ ecol,
    const float* __restrict__ W2, const float* __restrict__ b2,
    float* __restrict__ pred)
{
    int warp = (blockIdx.x * blockDim.x + threadIdx.x) >> 5;
    int lane = threadIdx.x & 31;
    if (warp >= NEL) return;

    int r = erow[warp];
    int c = ecol[warp];
    const float4 ug = *(const float4*)(g_ug + (size_t)r * CC + lane * 4);
    const float4 ud = *(const float4*)(g_ud + (size_t)c * CC + lane * 4);
    const float4 w2 = *(const float4*)(W2 + lane * 4);

    float s = fmaxf(ug.x + ud.x, 0.f) * w2.x
            + fmaxf(ug.y + ud.y, 0.f) * w2.y
            + fmaxf(ug.z + ud.z, 0.f) * w2.z
            + fmaxf(ug.w + ud.w, 0.f) * w2.w;

    #pragma unroll
    for (int o = 16; o > 0; o >>= 1)
        s += __shfl_xor_sync(0xFFFFFFFFu, s, o);

    if (lane == 0) pred[warp] = s + b2[0];
}

// ---------------------------------------------------------------------------
extern "C" void kernel_launch(void* const* d_in, const int* in_sizes, int n_in,
                              void* d_out, int out_size)
{
    (void)in_sizes; (void)n_in; (void)out_size;

    const float* x_gene    = (const float*)d_in[0];
    const float* x_disease = (const float*)d_in[1];
    const int*   ei_g2d    = (const int*)d_in[2];   // [2, E]: row0 src, row1 dst
    const int*   ei_d2g    = (const int*)d_in[3];
    // d_in[4], d_in[5]: edge_emb_* -- provably unused (softmax weights sum to 1)
    const int*   eli       = (const int*)d_in[6];   // [2, EL]
    const float* Wn_g      = (const float*)d_in[7];
    const float* bn_g      = (const float*)d_in[8];
    const float* Wn_d      = (const float*)d_in[9];
    const float* bn_d      = (const float*)d_in[10];
    // d_in[11..16]: We_*, be_*, att_w, att_b -- unused for same reason
    const float* W1        = (const float*)d_in[17];  // [256, 128]
    const float* b1        = (const float*)d_in[18];
    const float* W2        = (const float*)d_in[19];  // [128, 1]
    const float* b2        = (const float*)d_in[20];

    float* out   = (float*)d_out;
    float* pred  = out;                                // [EL]
    float* z_gen = out + NEL;                          // [NG, 128]
    float* z_dis = out + NEL + (size_t)NGN * CC;       // [ND, 128]

    float* ug_ptr; float* ud_ptr;
    unsigned char* mg_ptr; unsigned char* md_ptr;
    cudaGetSymbolAddress((void**)&ug_ptr, g_ug);
    cudaGetSymbolAddress((void**)&ud_ptr, g_ud);
    cudaGetSymbolAddress((void**)&mg_ptr, g_mask_g);
    cudaGetSymbolAddress((void**)&md_ptr, g_mask_d);

    // 1) isolation masks
    init_masks_kernel<<<(NGN + 255) / 256, 256>>>();
    scatter_masks_kernel<<<(NE + 255) / 256, 256>>>(ei_g2d + NE, ei_d2g + NE);

    const int grid_g = (NGN + MT - 1) / MT;
    const int grid_d = (NDN + MT - 1) / MT;

    // 2) z_gene = relu(x_gene @ Wn_g + bn_g) * mask_g ; z_disease likewise
    gemm128_kernel<<<grid_g, 256>>>(x_gene,    Wn_g, bn_g, mg_ptr, z_gen, NGN, 1);
    gemm128_kernel<<<grid_d, 256>>>(x_disease, Wn_d, bn_d, md_ptr, z_dis, NDN, 1);

    // 3) per-node MLP partials: u_g = z_gene @ W1[:128]; u_d = z_dis @ W1[128:] + b1
    gemm128_kernel<<<grid_g, 256>>>(z_gen, W1,           nullptr, nullptr, ug_ptr, NGN, 0);
    gemm128_kernel<<<grid_d, 256>>>(z_dis, W1 + CC * CC, b1,      nullptr, ud_ptr, NDN, 0);

    // 4) edge scores
    pred_kernel<<<(NEL * 32 + 255) / 256, 256>>>(eli, eli + NEL, W2, b2, pred);
}

// round 3
// speedup vs baseline: 1.1581x; 1.1581x over previous
#include <cuda_runtime.h>
#include <cstddef>

#define NGN 100000
#define NDN 100000
#define NE  400000
#define NEL 200000
#define CC  128

#define MT 128          // rows per block
#define KC 16           // k-chunk
#define NCHUNK (CC / KC)
#define AS_STRIDE 132   // as_t[k][row] row stride (floats), 16B aligned, bank-shifted

// Scratch (device globals; no allocation allowed in kernel_launch)
__device__ __align__(16) float g_ug[(size_t)NGN * CC];
__device__ __align__(16) float g_ud[(size_t)NDN * CC];
__device__ unsigned char g_mask_g[NGN];
__device__ unsigned char g_mask_d[NDN];

// ---------------------------------------------------------------------------
__global__ void init_masks_kernel() {
    int i = blockIdx.x * blockDim.x + threadIdx.x;
    if (i < NGN) g_mask_g[i] = 0;
    if (i < NDN) g_mask_d[i] = 0;
}

__global__ void scatter_masks_kernel(const int* __restrict__ dst_g2d,
                                     const int* __restrict__ dst_d2g) {
    int e = blockIdx.x * blockDim.x + threadIdx.x;
    if (e < NE) {
        g_mask_d[dst_g2d[e]] = 1;   // g2d edges land on diseases
        g_mask_g[dst_d2g[e]] = 1;   // d2g edges land on genes
    }
}

// ---------------------------------------------------------------------------
// GEMM: out[M,128] = act(A[M,128] @ W[128,128] + bias) (* mask if do_relu)
// 128x128 block tile, 256 threads, 8x8 microtile, KC=16, A stored k-major.
// ---------------------------------------------------------------------------
__global__ __launch_bounds__(256, 2) void gemm128_kernel(
    const float* __restrict__ A, const float* __restrict__ W,
    const float* __restrict__ bias, const unsigned char* __restrict__ mask,
    float* __restrict__ out, int M, int do_relu)
{
    __shared__ float as_t[KC][AS_STRIDE];  // transposed A chunk: [k][row]
    __shared__ float ws[KC][CC];           // W chunk: [k][n]

    const int tid = threadIdx.x;
    const int tx = tid & 15;               // 16 col groups (8 cols)
    const int ty = tid >> 4;               // 16 row groups (8 rows)
    const int row0 = blockIdx.x * MT;

    // A staging map: chunk = 128 rows x 16 k = 512 float4; 2 per thread
    const int ar = tid >> 2;               // 0..63 (and +64 for t=1)
    const int ak = (tid & 3) << 2;         // 0,4,8,12
    // W staging map: chunk = 16 k x 128 n = 512 float4; 2 per thread
    const int wk = tid >> 5;               // 0..7 (and +8)
    const int wn = (tid & 31) << 2;        // 0..124

    float acc[8][8];
    #pragma unroll
    for (int i = 0; i < 8; ++i)
        #pragma unroll
        for (int j = 0; j < 8; ++j) acc[i][j] = 0.0f;

    float4 pa[2], pw[2];

    // prefetch chunk 0 into registers
    {
        #pragma unroll
        for (int t = 0; t < 2; ++t) {
            int r = ar + t * 64;
            pa[t] = make_float4(0.f, 0.f, 0.f, 0.f);
            if (row0 + r < M)
                pa[t] = *(const float4*)(A + (size_t)(row0 + r) * CC + ak);
            pw[t] = *(const float4*)(W + (size_t)(wk + t * 8) * CC + wn);
        }
    }

    #pragma unroll
    for (int c = 0; c < NCHUNK; ++c) {
        // commit prefetched registers to smem
        #pragma unroll
        for (int t = 0; t < 2; ++t) {
            int r = ar + t * 64;
            as_t[ak + 0][r] = pa[t].x;
            as_t[ak + 1][r] = pa[t].y;
            as_t[ak + 2][r] = pa[t].z;
            as_t[ak + 3][r] = pa[t].w;
            *(float4*)&ws[wk + t * 8][wn] = pw[t];
        }
        __syncthreads();

        // prefetch next chunk while computing this one
        if (c < NCHUNK - 1) {
            int kc = (c + 1) * KC;
            #pragma unroll
            for (int t = 0; t < 2; ++t) {
                int r = ar + t * 64;
                pa[t] = make_float4(0.f, 0.f, 0.f, 0.f);
                if (row0 + r < M)
                    pa[t] = *(const float4*)(A + (size_t)(row0 + r) * CC + kc + ak);
                // k-chunk advances along W's ROW dimension:
                pw[t] = *(const float4*)(W + (size_t)(kc + wk + t * 8) * CC + wn);
            }
        }

        #pragma unroll
        for (int k = 0; k < KC; ++k) {
            const float4 a0 = *(const float4*)&as_t[k][ty * 8];
            const float4 a1 = *(const float4*)&as_t[k][ty * 8 + 4];
            const float4 w0 = *(const float4*)&ws[k][tx * 8];
            const float4 w1 = *(const float4*)&ws[k][tx * 8 + 4];
            const float av[8] = {a0.x, a0.y, a0.z, a0.w, a1.x, a1.y, a1.z, a1.w};
            const float wv[8] = {w0.x, w0.y, w0.z, w0.w, w1.x, w1.y, w1.z, w1.w};
            #pragma unroll
            for (int i = 0; i < 8; ++i)
                #pragma unroll
                for (int j = 0; j < 8; ++j)
                    acc[i][j] = fmaf(av[i], wv[j], acc[i][j]);
        }
        __syncthreads();
    }

    // Epilogue
    float bv[8];
    #pragma unroll
    for (int j = 0; j < 8; ++j)
        bv[j] = bias ? bias[tx * 8 + j] : 0.0f;

    #pragma unroll
    for (int i = 0; i < 8; ++i) {
        int r = row0 + ty * 8 + i;
        if (r < M) {
            float mm = 1.0f;
            if (do_relu && mask) mm = (float)mask[r];
            float o[8];
            #pragma unroll
            for (int j = 0; j < 8; ++j) {
                float v = acc[i][j] + bv[j];
                if (do_relu) v = fmaxf(v, 0.0f) * mm;
                o[j] = v;
            }
            float* dst = out + (size_t)r * CC + tx * 8;
            *(float4*)dst       = make_float4(o[0], o[1], o[2], o[3]);
            *(float4*)(dst + 4) = make_float4(o[4], o[5], o[6], o[7]);
        }
    }
}

// ---------------------------------------------------------------------------
// Link prediction head: one warp per labeled edge.
// pred[e] = relu(u_g[row[e]] + u_d[col[e]]) . W2 + b2     (b1 folded into u_d)
// ---------------------------------------------------------------------------
__global__ __launch_bounds__(256) void pred_kernel(
    const int* __restrict__ erow, const int* __restrict__ ecol,
    const float* __restrict__ W2, const float* __restrict__ b2,
    float* __restrict__ pred)
{
    int warp = (blockIdx.x * blockDim.x + threadIdx.x) >> 5;
    int lane = threadIdx.x & 31;
    if (warp >= NEL) return;

    int r = erow[warp];
    int c = ecol[warp];
    const float4 ug = *(const float4*)(g_ug + (size_t)r * CC + lane * 4);
    const float4 ud = *(const float4*)(g_ud + (size_t)c * CC + lane * 4);
    const float4 w2 = *(const float4*)(W2 + lane * 4);

    float s = fmaxf(ug.x + ud.x, 0.f) * w2.x
            + fmaxf(ug.y + ud.y, 0.f) * w2.y
            + fmaxf(ug.z + ud.z, 0.f) * w2.z
            + fmaxf(ug.w + ud.w, 0.f) * w2.w;

    #pragma unroll
    for (int o = 16; o > 0; o >>= 1)
        s += __shfl_xor_sync(0xFFFFFFFFu, s, o);

    if (lane == 0) pred[warp] = s + b2[0];
}

// ---------------------------------------------------------------------------
extern "C" void kernel_launch(void* const* d_in, const int* in_sizes, int n_in,
                              void* d_out, int out_size)
{
    (void)in_sizes; (void)n_in; (void)out_size;

    const float* x_gene    = (const float*)d_in[0];
    const float* x_disease = (const float*)d_in[1];
    const int*   ei_g2d    = (const int*)d_in[2];   // [2, E]: row0 src, row1 dst
    const int*   ei_d2g    = (const int*)d_in[3];
    // d_in[4], d_in[5]: edge_emb_* -- provably unused (softmax weights sum to 1)
    const int*   eli       = (const int*)d_in[6];   // [2, EL]
    const float* Wn_g      = (const float*)d_in[7];
    const float* bn_g      = (const float*)d_in[8];
    const float* Wn_d      = (const float*)d_in[9];
    const float* bn_d      = (const float*)d_in[10];
    // d_in[11..16]: We_*, be_*, att_w, att_b -- unused for same reason
    const float* W1        = (const float*)d_in[17];  // [256, 128]
    const float* b1        = (const float*)d_in[18];
    const float* W2        = (const float*)d_in[19];  // [128, 1]
    const float* b2        = (const float*)d_in[20];

    float* out   = (float*)d_out;
    float* pred  = out;                                // [EL]
    float* z_gen = out + NEL;                          // [NG, 128]
    float* z_dis = out + NEL + (size_t)NGN * CC;       // [ND, 128]

    float* ug_ptr; float* ud_ptr;
    unsigned char* mg_ptr; unsigned char* md_ptr;
    cudaGetSymbolAddress((void**)&ug_ptr, g_ug);
    cudaGetSymbolAddress((void**)&ud_ptr, g_ud);
    cudaGetSymbolAddress((void**)&mg_ptr, g_mask_g);
    cudaGetSymbolAddress((void**)&md_ptr, g_mask_d);

    // 1) isolation masks
    init_masks_kernel<<<(NGN + 255) / 256, 256>>>();
    scatter_masks_kernel<<<(NE + 255) / 256, 256>>>(ei_g2d + NE, ei_d2g + NE);

    const int grid_g = (NGN + MT - 1) / MT;
    const int grid_d = (NDN + MT - 1) / MT;

    // Order for L2 reuse: consume each z right after producing it.
    gemm128_kernel<<<grid_g, 256>>>(x_gene,    Wn_g, bn_g, mg_ptr, z_gen, NGN, 1);
    gemm128_kernel<<<grid_g, 256>>>(z_gen, W1,           nullptr, nullptr, ug_ptr, NGN, 0);
    gemm128_kernel<<<grid_d, 256>>>(x_disease, Wn_d, bn_d, md_ptr, z_dis, NDN, 1);
    gemm128_kernel<<<grid_d, 256>>>(z_dis, W1 + CC * CC, b1,      nullptr, ud_ptr, NDN, 0);

    // 4) edge scores
    pred_kernel<<<(NEL * 32 + 255) / 256, 256>>>(eli, eli + NEL, W2, b2, pred);
}